// round 5
// baseline (speedup 1.0000x reference)
#include <cuda_runtime.h>

static constexpr int B = 256;
static constexpr int S = 2048;
static constexpr int T = 48;

typedef unsigned long long u64;

// ---- packed f32x2 helpers (Blackwell FFMA2: only reachable via PTX) ----
__device__ __forceinline__ u64 pack2(float x, float y) {
    u64 r; asm("mov.b64 %0, {%1, %2};" : "=l"(r) : "f"(x), "f"(y)); return r;
}
__device__ __forceinline__ void unpack2(u64 v, float& x, float& y) {
    asm("mov.b64 {%0, %1}, %2;" : "=f"(x), "=f"(y) : "l"(v));
}
__device__ __forceinline__ u64 ffma2(u64 a, u64 b, u64 c) {
    u64 d; asm("fma.rn.f32x2 %0, %1, %2, %3;" : "=l"(d) : "l"(a), "l"(b), "l"(c)); return d;
}
__device__ __forceinline__ u64 fmul2(u64 a, u64 b) {
    u64 d; asm("mul.rn.f32x2 %0, %1, %2;" : "=l"(d) : "l"(a), "l"(b)); return d;
}
__device__ __forceinline__ u64 fadd2(u64 a, u64 b) {
    u64 d; asm("add.rn.f32x2 %0, %1, %2;" : "=l"(d) : "l"(a), "l"(b)); return d;
}

// One scaled-exp-domain semiring chain. BW=0: alpha forward (matvec then
// *exp(e)). BW=1: beta backward (*exp(e) then matvec). Lane l owns states
// (2l, 2l+1); lanes 24..31 padding (E rows 0 -> p identically 0, their
// broadcast slots never read).
// reset_i >= 0: at iteration reset_i, exactly lane0-normalize the vector and
// zero the accumulated scale (Perron-Frobenius stitch boundary).
template<int BW>
__device__ __forceinline__ void run_chain(
    const float* __restrict__ ep,    // adjusted emission base (+ j0)
    const u64 (&E)[48],
    u64 p, int niter, int reset_i, int lane,
    float4 (*buf)[32],               // per-warp double buffer [2][32]
    u64& pOut, float& cOut)
{
    int cexp = 0;                    // accumulated power-of-two scale
    float2 ebuf[8];
    int cb = 0;

#define E_OFF(i) ( BW ? (size_t)(S - 1 - (i)) * T : (size_t)((i) + 1) * T )

#pragma unroll
    for (int u = 0; u < 8; ++u)
        if (u < niter) ebuf[u] = *(const float2*)(ep + E_OFF(u));

#define BODY(i, u, RENORM) do {                                            \
    float2 e = ebuf[u];                                                    \
    int tn = (i) + 8;                                                      \
    if (tn < niter) ebuf[u] = *(const float2*)(ep + E_OFF(tn));            \
    float fex = __expf(e.x);                                               \
    float fey = __expf(e.y);                                               \
    u64 Fe = pack2(fex, fey);                                              \
    u64 src = BW ? fmul2(p, Fe) : p;                                       \
    float sx, sy; unpack2(src, sx, sy);                                    \
    buf[cb][lane] = make_float4(sx, sx, sy, sy);                           \
    __syncwarp();                                                          \
    u64 a0=0ull,a1=0ull,a2=0ull,a3=0ull,a4=0ull,a5=0ull,a6=0ull,a7=0ull;   \
    _Pragma("unroll")                                                      \
    for (int k = 0; k < 24; k += 4) {                                      \
        float4 v0 = buf[cb][k];                                            \
        a0 = ffma2(E[2*k  ], pack2(v0.x, v0.y), a0);                       \
        a1 = ffma2(E[2*k+1], pack2(v0.z, v0.w), a1);                       \
        float4 v1 = buf[cb][k+1];                                          \
        a2 = ffma2(E[2*k+2], pack2(v1.x, v1.y), a2);                       \
        a3 = ffma2(E[2*k+3], pack2(v1.z, v1.w), a3);                       \
        float4 v2 = buf[cb][k+2];                                          \
        a4 = ffma2(E[2*k+4], pack2(v2.x, v2.y), a4);                       \
        a5 = ffma2(E[2*k+5], pack2(v2.z, v2.w), a5);                       \
        float4 v3 = buf[cb][k+3];                                          \
        a6 = ffma2(E[2*k+6], pack2(v3.x, v3.y), a6);                       \
        a7 = ffma2(E[2*k+7], pack2(v3.z, v3.w), a7);                       \
    }                                                                      \
    u64 q = fadd2(fadd2(fadd2(a0, a1), fadd2(a2, a3)),                     \
                  fadd2(fadd2(a4, a5), fadd2(a6, a7)));                    \
    p = BW ? q : fmul2(q, Fe);                                             \
    cb ^= 1;                                                               \
    if (RENORM) {                                                          \
        if ((i) == reset_i) {                                              \
            float px_, py_; unpack2(p, px_, py_);                          \
            float ref = __shfl_sync(0xffffffffu, px_, 0);                  \
            float inv = __fdividef(1.f, ref);                              \
            p = fmul2(p, pack2(inv, inv));                                 \
            cexp = 0;                       /* stitch boundary: discard */ \
        } else {                                                           \
            float px_, py_; unpack2(p, px_, py_);                          \
            float ref = __shfl_sync(0xffffffffu, px_, 0);                  \
            int ex = (__float_as_int(ref) >> 23) & 255;                    \
            float sc = __int_as_float((254 - ex) << 23); /* 2^(127-ex) */  \
            p = fmul2(p, pack2(sc, sc));                                   \
            cexp += ex - 127;                                              \
        }                                                                  \
    }                                                                      \
} while (0)

    int nmain = niter & ~7;
    for (int i = 0; i < nmain; i += 8) {
#pragma unroll
        for (int u = 0; u < 8; ++u) BODY(i + u, u, (u == 7));
    }
#pragma unroll
    for (int u = 0; u < 8; ++u)
        if (nmain + u < niter) BODY(nmain + u, u, false);

    // final exact renorm (lane0-normalize) + exact log of scale
    float c = (float)cexp * 0.69314718055994531f;
    {
        float px_, py_; unpack2(p, px_, py_);
        float ref = __shfl_sync(0xffffffffu, px_, 0);
        float inv = __fdividef(1.f, ref);
        p = fmul2(p, pack2(inv, inv));
        c += __logf(ref);
    }
    pOut = p; cOut = c;
#undef BODY
#undef E_OFF
}

// Segment plan per sequence (Perron-Frobenius 4-way split, burn-in L=48):
//   w0 fw-exact : iters 1..511   (511)  -> scale c0 of alpha_511
//   w1 fw-burn  : iters 464..1023 (560), reset at local iter 47 (t=511)
//                 -> direction alpha_1023 + scale c1 (511->1023)
//   w2 bw-burn  : emissions 1583..1024 (560), reset at local iter 47 (t=1536)
//                 -> direction beta_1024 + scale c2 (1536->1024)
//   w3 bw-exact : emissions 2047..1536 (512) -> scale c3 of beta_1536
// Z = log(alpha_1023 . beta_1024) + c0 + c1 + c2 + c3
__global__ void __launch_bounds__(128)
crf_kernel(const float* __restrict__ emis,
           const int*   __restrict__ tagsw,   // int32 view; int64 auto-detected
           const int*   __restrict__ mask,
           const float* __restrict__ trans,
           const float* __restrict__ startT,
           const float* __restrict__ endT,
           float* __restrict__ out)
{
    __shared__ float4 bufs[4][2][32];   // [warp][double-buffer][lane]
    __shared__ float shP[48], shR[48], shC[4];
    __shared__ float shRed[128];

    const int b   = blockIdx.x;
    const int tid = threadIdx.x;
    const int w   = tid >> 5;
    const int l   = tid & 31;
    const bool act = l < 24;
    const int j0 = act ? 2*l     : 0;
    const int j1 = act ? 2*l + 1 : 0;

    const size_t base = (size_t)b * S * T;

    // per-lane exp(transition) constants in registers (96 regs)
    u64 E[48];
    if (w < 2) {
#pragma unroll
        for (int i = 0; i < 48; ++i) {      // fw: column pairs E[i][j0], E[i][j1]
            float a  = __expf(trans[i*T + j0]);
            float bb = __expf(trans[i*T + j1]);
            E[i] = act ? pack2(a, bb) : 0ull;
        }
    } else {
#pragma unroll
        for (int j = 0; j < 48; ++j) {      // bw: row pairs E[j0][j], E[j1][j]
            float a  = __expf(trans[j0*T + j]);
            float bb = __expf(trans[j1*T + j]);
            E[j] = act ? pack2(a, bb) : 0ull;
        }
    }

    const float* ep0 = emis + base + j0;

    u64 pfin; float cfin;
    if (w == 0) {
        float2 e0 = *(const float2*)(ep0);                    // t = 0
        u64 p0 = act ? pack2(__expf(startT[j0] + e0.x),
                             __expf(startT[j1] + e0.y)) : 0ull;
        run_chain<0>(ep0, E, p0, 511, -1, l, bufs[0], pfin, cfin);
    } else if (w == 1) {
        u64 p0 = act ? pack2(1.f, 1.f) : 0ull;                // uniform burn-in
        run_chain<0>(ep0 + (size_t)463 * T, E, p0, 560, 47, l, bufs[1], pfin, cfin);
    } else if (w == 2) {
        u64 p0 = act ? pack2(1.f, 1.f) : 0ull;                // uniform burn-in
        run_chain<1>(ep0 - (size_t)464 * T, E, p0, 560, 47, l, bufs[2], pfin, cfin);
    } else {
        u64 p0 = act ? pack2(__expf(endT[j0]), __expf(endT[j1])) : 0ull;
        run_chain<1>(ep0, E, p0, 512, -1, l, bufs[3], pfin, cfin);
    }

    if (act) {
        float px, py; unpack2(pfin, px, py);
        if (w == 1) { shP[2*l] = px; shP[2*l+1] = py; }       // alpha_1023 dir
        if (w == 2) { shR[2*l] = px; shR[2*l+1] = py; }       // beta_1024 dir
    }
    if (l == 0) shC[w] = cfin;
    __syncthreads();

    shRed[tid] = (tid < 48) ? shP[tid] * shR[tid] : 0.f;
    __syncthreads();

    float Z = 0.f;
    if (tid == 0) {
        float dot = 0.f;
#pragma unroll
        for (int k = 0; k < 48; ++k) dot += shRed[k];
        Z = __logf(dot) + shC[0] + shC[1] + shC[2] + shC[3];
    }

    // ---- tags dtype detection: int64 iff sampled odd 32-bit words all zero ----
    int oddw = tagsw[2*tid + 1];
    int any  = __syncthreads_or(oddw != 0);          // also a barrier for shRed reuse
    const bool is64 = (any == 0);

    // ---- numerator: gold-path score ----
    const size_t tbase = (size_t)b * S;
    float num = 0.f;
#pragma unroll 4
    for (int k = 0; k < 16; ++k) {
        int s = tid + 128*k;
        int cur = is64 ? tagsw[(tbase + s) * 2] : tagsw[tbase + s];
        if (s == 0) {
            num += startT[cur] + emis[base + cur];
        } else {
            int prev = is64 ? tagsw[(tbase + s - 1) * 2] : tagsw[tbase + s - 1];
            float m = (float)mask[tbase + s];
            num += (trans[prev*T + cur] + emis[base + (size_t)s*T + cur]) * m;
        }
        if (s == S - 1) num += endT[cur];
    }
    shRed[tid] = num;
    __syncthreads();
    if (tid == 0) {
        float tot = 0.f;
#pragma unroll
        for (int k = 0; k < 128; ++k) tot += shRed[k];
        out[b] = Z - tot;                            // NLL
    }
}

extern "C" void kernel_launch(void* const* d_in, const int* in_sizes, int n_in,
                              void* d_out, int out_size) {
    (void)in_sizes; (void)n_in; (void)out_size;
    crf_kernel<<<B, 128>>>(
        (const float*)d_in[0],   // emissions
        (const int*)  d_in[1],   // tags (i32 or i64, detected on device)
        (const int*)  d_in[2],   // mask
        (const float*)d_in[3],   // transitions
        (const float*)d_in[4],   // start_transitions
        (const float*)d_in[5],   // end_transitions
        (float*)d_out);
}

// round 6
// speedup vs baseline: 2.0860x; 2.0860x over previous
#include <cuda_runtime.h>

static constexpr int B = 256;
static constexpr int S = 2048;
static constexpr int T = 48;

typedef unsigned long long u64;

// ---- packed f32x2 helpers (Blackwell FFMA2: only reachable via PTX) ----
__device__ __forceinline__ u64 pack2(float x, float y) {
    u64 r; asm("mov.b64 %0, {%1, %2};" : "=l"(r) : "f"(x), "f"(y)); return r;
}
__device__ __forceinline__ void unpack2(u64 v, float& x, float& y) {
    asm("mov.b64 {%0, %1}, %2;" : "=f"(x), "=f"(y) : "l"(v));
}
__device__ __forceinline__ u64 ffma2(u64 a, u64 b, u64 c) {
    u64 d; asm("fma.rn.f32x2 %0, %1, %2, %3;" : "=l"(d) : "l"(a), "l"(b), "l"(c)); return d;
}
__device__ __forceinline__ u64 fmul2(u64 a, u64 b) {
    u64 d; asm("mul.rn.f32x2 %0, %1, %2;" : "=l"(d) : "l"(a), "l"(b)); return d;
}
__device__ __forceinline__ u64 fadd2(u64 a, u64 b) {
    u64 d; asm("add.rn.f32x2 %0, %1, %2;" : "=l"(d) : "l"(a), "l"(b)); return d;
}

// One scaled-exp-domain semiring chain. BW=0: alpha forward (matvec then
// *exp(e)). BW=1: beta backward (*exp(e) then matvec). Lane l owns states
// (2l, 2l+1); lanes 24..31 padding (E rows 0 -> p identically 0).
// niter / reset_i are RUNTIME so each BW direction inlines exactly ONCE
// (4 compile-time instances destroyed the compiler's prefetch pipelining in R5).
// reset_i >= 0: at that iteration lane0-normalize and zero the scale
// (Perron-Frobenius stitch boundary).
template<int BW>
__device__ __forceinline__ void run_chain(
    const float* __restrict__ ep,    // adjusted emission base (+ j0)
    const u64 (&E)[48],
    u64 p, int niter, int reset_i, int lane,
    float4 (*buf)[32],               // per-warp double buffer [2][32]
    u64& pOut, float& cOut)
{
    int cexp = 0;                    // accumulated power-of-two scale
    float2 ebuf[8];
    int cb = 0;

#define E_OFF(i) ( BW ? (size_t)(S - 1 - (i)) * T : (size_t)((i) + 1) * T )

#pragma unroll
    for (int u = 0; u < 8; ++u)
        ebuf[u] = *(const float2*)(ep + E_OFF(u));   // niter >= 511 always

#define BODY(i, u, RENORM) do {                                            \
    float2 e = ebuf[u];                                                    \
    int tn = (i) + 8;                                                      \
    if (tn < niter) ebuf[u] = *(const float2*)(ep + E_OFF(tn));            \
    float fex = __expf(e.x);                                               \
    float fey = __expf(e.y);                                               \
    u64 Fe = pack2(fex, fey);                                              \
    u64 src = BW ? fmul2(p, Fe) : p;                                       \
    float sx, sy; unpack2(src, sx, sy);                                    \
    buf[cb][lane] = make_float4(sx, sx, sy, sy);                           \
    __syncwarp();                                                          \
    u64 a0=0ull,a1=0ull,a2=0ull,a3=0ull,a4=0ull,a5=0ull,a6=0ull,a7=0ull;   \
    _Pragma("unroll")                                                      \
    for (int k = 0; k < 24; k += 4) {                                      \
        float4 v0 = buf[cb][k];                                            \
        a0 = ffma2(E[2*k  ], pack2(v0.x, v0.y), a0);                       \
        a1 = ffma2(E[2*k+1], pack2(v0.z, v0.w), a1);                       \
        float4 v1 = buf[cb][k+1];                                          \
        a2 = ffma2(E[2*k+2], pack2(v1.x, v1.y), a2);                       \
        a3 = ffma2(E[2*k+3], pack2(v1.z, v1.w), a3);                       \
        float4 v2 = buf[cb][k+2];                                          \
        a4 = ffma2(E[2*k+4], pack2(v2.x, v2.y), a4);                       \
        a5 = ffma2(E[2*k+5], pack2(v2.z, v2.w), a5);                       \
        float4 v3 = buf[cb][k+3];                                          \
        a6 = ffma2(E[2*k+6], pack2(v3.x, v3.y), a6);                       \
        a7 = ffma2(E[2*k+7], pack2(v3.z, v3.w), a7);                       \
    }                                                                      \
    u64 q = fadd2(fadd2(fadd2(a0, a1), fadd2(a2, a3)),                     \
                  fadd2(fadd2(a4, a5), fadd2(a6, a7)));                    \
    p = BW ? q : fmul2(q, Fe);                                             \
    cb ^= 1;                                                               \
    if (RENORM) {                                                          \
        float px_, py_; unpack2(p, px_, py_);                              \
        float ref = __shfl_sync(0xffffffffu, px_, 0);                      \
        if ((i) == reset_i) {                                              \
            float inv = __fdividef(1.f, ref);                              \
            p = fmul2(p, pack2(inv, inv));                                 \
            cexp = 0;                       /* stitch boundary: discard */ \
        } else {                                                           \
            int ex = (__float_as_int(ref) >> 23) & 255;                    \
            float sc = __int_as_float((254 - ex) << 23); /* 2^(127-ex) */  \
            p = fmul2(p, pack2(sc, sc));                                   \
            cexp += ex - 127;                                              \
        }                                                                  \
    }                                                                      \
} while (0)

    int nmain = niter & ~7;
    for (int i = 0; i < nmain; i += 8) {
#pragma unroll
        for (int u = 0; u < 8; ++u) BODY(i + u, u, (u == 7));
    }
#pragma unroll
    for (int u = 0; u < 8; ++u)
        if (nmain + u < niter) BODY(nmain + u, u, false);

    // final exact renorm (lane0-normalize) + exact log of scale
    float c = (float)cexp * 0.69314718055994531f;
    {
        float px_, py_; unpack2(p, px_, py_);
        float ref = __shfl_sync(0xffffffffu, px_, 0);
        float inv = __fdividef(1.f, ref);
        p = fmul2(p, pack2(inv, inv));
        c += __logf(ref);
    }
    pOut = p; cOut = c;
#undef BODY
#undef E_OFF
}

// Segment plan per sequence (Perron-Frobenius 4-way split, burn-in L=48):
//   w0 fw-exact : iters 1..511   (511)  -> scale c0 of alpha_511
//   w1 fw-burn  : t=464..1023 (560), reset at local iter 47 (after t=511)
//                 -> direction alpha_1023 + scale c1 (511->1023)
//   w2 bw-burn  : t=1583..1024 (560), reset at local iter 47 (after t=1536)
//                 -> direction beta_1024 + scale c2 (1536->1024)
//   w3 bw-exact : t=2047..1536 (512) -> scale c3 of beta_1536
// Z = log(alpha_1023 . beta_1024) + c0 + c1 + c2 + c3
__global__ void __launch_bounds__(128)
crf_kernel(const float* __restrict__ emis,
           const int*   __restrict__ tagsw,   // int32 view; int64 auto-detected
           const int*   __restrict__ mask,
           const float* __restrict__ trans,
           const float* __restrict__ startT,
           const float* __restrict__ endT,
           float* __restrict__ out)
{
    __shared__ float4 bufs[4][2][32];   // [warp][double-buffer][lane]
    __shared__ float shP[48], shR[48], shC[4];
    __shared__ float shRed[128];

    const int b   = blockIdx.x;
    const int tid = threadIdx.x;
    const int w   = tid >> 5;
    const int l   = tid & 31;
    const bool act = l < 24;
    const int j0 = act ? 2*l     : 0;
    const int j1 = act ? 2*l + 1 : 0;

    const size_t base = (size_t)b * S * T;

    // per-lane exp(transition) constants in registers (96 regs)
    u64 E[48];
    if (w < 2) {
#pragma unroll
        for (int i = 0; i < 48; ++i) {      // fw: column pairs E[i][j0], E[i][j1]
            float a  = __expf(trans[i*T + j0]);
            float bb = __expf(trans[i*T + j1]);
            E[i] = act ? pack2(a, bb) : 0ull;
        }
    } else {
#pragma unroll
        for (int j = 0; j < 48; ++j) {      // bw: row pairs E[j0][j], E[j1][j]
            float a  = __expf(trans[j0*T + j]);
            float bb = __expf(trans[j1*T + j]);
            E[j] = act ? pack2(a, bb) : 0ull;
        }
    }

    const float* ep0 = emis + base + j0;

    // runtime per-warp chain parameters (keeps ONE run_chain instance per BW)
    const bool exact = (w == 0) || (w == 3);
    const int  niter = (w == 0) ? 511 : (w == 3) ? 512 : 560;
    const int  reset = exact ? -1 : 47;

    u64 pfin; float cfin;
    if (w < 2) {
        u64 p0;
        const float* ep;
        if (w == 0) {
            float2 e0 = *(const float2*)(ep0);                // t = 0
            p0 = act ? pack2(__expf(startT[j0] + e0.x),
                             __expf(startT[j1] + e0.y)) : 0ull;
            ep = ep0;
        } else {
            p0 = act ? pack2(1.f, 1.f) : 0ull;                // uniform burn-in
            ep = ep0 + (size_t)463 * T;
        }
        run_chain<0>(ep, E, p0, niter, reset, l, bufs[w], pfin, cfin);
    } else {
        u64 p0;
        const float* ep;
        if (w == 3) {
            p0 = act ? pack2(__expf(endT[j0]), __expf(endT[j1])) : 0ull;
            ep = ep0;
        } else {
            p0 = act ? pack2(1.f, 1.f) : 0ull;                // uniform burn-in
            ep = ep0 - (size_t)464 * T;
        }
        run_chain<1>(ep, E, p0, niter, reset, l, bufs[w], pfin, cfin);
    }

    if (act) {
        float px, py; unpack2(pfin, px, py);
        if (w == 1) { shP[2*l] = px; shP[2*l+1] = py; }       // alpha_1023 dir
        if (w == 2) { shR[2*l] = px; shR[2*l+1] = py; }       // beta_1024 dir
    }
    if (l == 0) shC[w] = cfin;
    __syncthreads();

    shRed[tid] = (tid < 48) ? shP[tid] * shR[tid] : 0.f;
    __syncthreads();

    float Z = 0.f;
    if (tid == 0) {
        float dot = 0.f;
#pragma unroll
        for (int k = 0; k < 48; ++k) dot += shRed[k];
        Z = __logf(dot) + shC[0] + shC[1] + shC[2] + shC[3];
    }

    // ---- tags dtype detection: int64 iff sampled odd 32-bit words all zero ----
    int oddw = tagsw[2*tid + 1];
    int any  = __syncthreads_or(oddw != 0);          // also a barrier for shRed reuse
    const bool is64 = (any == 0);

    // ---- numerator: gold-path score ----
    const size_t tbase = (size_t)b * S;
    float num = 0.f;
#pragma unroll 4
    for (int k = 0; k < 16; ++k) {
        int s = tid + 128*k;
        int cur = is64 ? tagsw[(tbase + s) * 2] : tagsw[tbase + s];
        if (s == 0) {
            num += startT[cur] + emis[base + cur];
        } else {
            int prev = is64 ? tagsw[(tbase + s - 1) * 2] : tagsw[tbase + s - 1];
            float m = (float)mask[tbase + s];
            num += (trans[prev*T + cur] + emis[base + (size_t)s*T + cur]) * m;
        }
        if (s == S - 1) num += endT[cur];
    }
    shRed[tid] = num;
    __syncthreads();
    if (tid == 0) {
        float tot = 0.f;
#pragma unroll
        for (int k = 0; k < 128; ++k) tot += shRed[k];
        out[b] = Z - tot;                            // NLL
    }
}

extern "C" void kernel_launch(void* const* d_in, const int* in_sizes, int n_in,
                              void* d_out, int out_size) {
    (void)in_sizes; (void)n_in; (void)out_size;
    crf_kernel<<<B, 128>>>(
        (const float*)d_in[0],   // emissions
        (const int*)  d_in[1],   // tags (i32 or i64, detected on device)
        (const int*)  d_in[2],   // mask
        (const float*)d_in[3],   // transitions
        (const float*)d_in[4],   // start_transitions
        (const float*)d_in[5],   // end_transitions
        (float*)d_out);
}

// round 7
// speedup vs baseline: 2.6420x; 1.2665x over previous
#include <cuda_runtime.h>

static constexpr int B = 256;
static constexpr int S = 2048;
static constexpr int T = 48;

typedef unsigned long long u64;

// ---- packed f32x2 helpers (Blackwell FFMA2: only reachable via PTX) ----
__device__ __forceinline__ u64 pack2(float x, float y) {
    u64 r; asm("mov.b64 %0, {%1, %2};" : "=l"(r) : "f"(x), "f"(y)); return r;
}
__device__ __forceinline__ void unpack2(u64 v, float& x, float& y) {
    asm("mov.b64 {%0, %1}, %2;" : "=f"(x), "=f"(y) : "l"(v));
}
__device__ __forceinline__ u64 ffma2(u64 a, u64 b, u64 c) {
    u64 d; asm("fma.rn.f32x2 %0, %1, %2, %3;" : "=l"(d) : "l"(a), "l"(b), "l"(c)); return d;
}
__device__ __forceinline__ u64 fadd2(u64 a, u64 b) {
    u64 d; asm("add.rn.f32x2 %0, %1, %2;" : "=l"(d) : "l"(a), "l"(b)); return d;
}

// One scaled-exp-domain semiring chain with TRANSPOSED pair packing:
// output j0 accumulates over source pairs: acc_j0 += (E[2k][j0],E[2k+1][j0])
// (x) (s_2k, s_2k+1). The b-operand is lane k's natural (sx,sy) float2 -> no
// duplicated broadcast; 1 STS.64 + 12 broadcast LDS.128 per step.
// BW=0: alpha forward (matvec then *exp(e)). BW=1: beta backward (*exp(e)
// then matvec). Lane l owns states (2l, 2l+1); lanes 24..31 padding (E pairs
// zero -> state identically 0; their buf slots never read).
// niter / reset_i / ep are RUNTIME so each BW direction inlines exactly ONCE
// (multiple compile-time instances destroy prefetch pipelining - R5 lesson).
// reset_i >= 0: lane0-normalize there and zero scale (PF stitch boundary).
template<int BW>
__device__ __forceinline__ void run_chain(
    const float* __restrict__ ep,    // adjusted emission base (+ j0)
    const u64 (&EA)[24], const u64 (&EB)[24],
    float px, float py, int niter, int reset_i, int lane,
    float2 (*buf)[32],               // per-warp double buffer [2][32]
    float& pxOut, float& pyOut, float& cOut)
{
    int cexp = 0;                    // accumulated power-of-two scale
    float2 ebuf[8];
    int cb = 0;

#define E_OFF(i) ( BW ? (size_t)(S - 1 - (i)) * T : (size_t)((i) + 1) * T )

#pragma unroll
    for (int u = 0; u < 8; ++u)
        ebuf[u] = *(const float2*)(ep + E_OFF(u));   // niter >= 341 always

#define BODY(i, u, RENORM) do {                                            \
    float2 e = ebuf[u];                                                    \
    int tn = (i) + 8;                                                      \
    if (tn < niter) ebuf[u] = *(const float2*)(ep + E_OFF(tn));            \
    float fex = __expf(e.x);                                               \
    float fey = __expf(e.y);                                               \
    float sx = BW ? px * fex : px;                                         \
    float sy = BW ? py * fey : py;                                         \
    buf[cb][lane] = make_float2(sx, sy);                                   \
    __syncwarp();                                                          \
    u64 a0=0ull,a1=0ull,a2=0ull,a3=0ull,a4=0ull,a5=0ull,a6=0ull,a7=0ull;   \
    const float4* bv = (const float4*)buf[cb];                             \
    _Pragma("unroll")                                                      \
    for (int m = 0; m < 12; m += 4) {                                      \
        float4 v0 = bv[m];                                                 \
        u64 b0 = pack2(v0.x, v0.y), b1 = pack2(v0.z, v0.w);                \
        a0 = ffma2(EA[2*m  ], b0, a0);  a4 = ffma2(EB[2*m  ], b0, a4);     \
        a1 = ffma2(EA[2*m+1], b1, a1);  a5 = ffma2(EB[2*m+1], b1, a5);     \
        float4 v1 = bv[m+1];                                               \
        u64 b2 = pack2(v1.x, v1.y), b3 = pack2(v1.z, v1.w);                \
        a2 = ffma2(EA[2*m+2], b2, a2);  a6 = ffma2(EB[2*m+2], b2, a6);     \
        a3 = ffma2(EA[2*m+3], b3, a3);  a7 = ffma2(EB[2*m+3], b3, a7);     \
        float4 v2 = bv[m+2];                                               \
        u64 b4 = pack2(v2.x, v2.y), b5 = pack2(v2.z, v2.w);                \
        a0 = ffma2(EA[2*m+4], b4, a0);  a4 = ffma2(EB[2*m+4], b4, a4);     \
        a1 = ffma2(EA[2*m+5], b5, a1);  a5 = ffma2(EB[2*m+5], b5, a5);     \
        float4 v3 = bv[m+3];                                               \
        u64 b6 = pack2(v3.x, v3.y), b7 = pack2(v3.z, v3.w);                \
        a2 = ffma2(EA[2*m+6], b6, a2);  a6 = ffma2(EB[2*m+6], b6, a6);     \
        a3 = ffma2(EA[2*m+7], b7, a3);  a7 = ffma2(EB[2*m+7], b7, a7);     \
    }                                                                      \
    u64 q0 = fadd2(fadd2(a0, a1), fadd2(a2, a3));                          \
    u64 q1 = fadd2(fadd2(a4, a5), fadd2(a6, a7));                          \
    float x0, y0; unpack2(q0, x0, y0);                                     \
    float x1, y1; unpack2(q1, x1, y1);                                     \
    float n0 = x0 + y0, n1 = x1 + y1;                                      \
    px = BW ? n0 : n0 * fex;                                               \
    py = BW ? n1 : n1 * fey;                                               \
    cb ^= 1;                                                               \
    if (RENORM) {                                                          \
        float ref = __shfl_sync(0xffffffffu, px, 0);                       \
        if ((i) == reset_i) {                                              \
            float inv = __fdividef(1.f, ref);                              \
            px *= inv; py *= inv;                                          \
            cexp = 0;                       /* stitch boundary: discard */ \
        } else {                                                           \
            int ex = (__float_as_int(ref) >> 23) & 255;                    \
            float sc = __int_as_float((254 - ex) << 23); /* 2^(127-ex) */  \
            px *= sc; py *= sc;                                            \
            cexp += ex - 127;                                              \
        }                                                                  \
    }                                                                      \
} while (0)

    int nmain = niter & ~7;
    for (int i = 0; i < nmain; i += 8) {
#pragma unroll
        for (int u = 0; u < 8; ++u) BODY(i + u, u, (u == 7));
    }
#pragma unroll
    for (int u = 0; u < 8; ++u)
        if (nmain + u < niter) BODY(nmain + u, u, false);

    // final exact renorm (lane0-normalize) + exact log of scale
    float c = (float)cexp * 0.69314718055994531f;
    {
        float ref = __shfl_sync(0xffffffffu, px, 0);
        float inv = __fdividef(1.f, ref);
        px *= inv; py *= inv;
        c += __logf(ref);
    }
    pxOut = px; pyOut = py; cOut = c;
#undef BODY
#undef E_OFF
}

// Perron-Frobenius 6-way split per sequence, burn-in 32:
//  w0 fw-exact t=1..341            (341)            -> c0
//  w1 fw-burn  t=310..682  reset@t=341 (i=31)  (373) -> c1
//  w2 fw-burn  t=651..1023 reset@t=682 (i=31)  (373) -> dir(alpha_1023)+c2
//  w3 bw-exact e=2047..1707        (341)            -> c3
//  w4 bw-burn  e=1738..1365 reset@e=1707 (i=31) (374) -> c4
//  w5 bw-burn  e=1396..1024 reset@e=1365 (i=31) (373) -> dir(beta_1024)+c5
// Z = log(dir_alpha . dir_beta) + c0+c1+c2+c3+c4+c5
__global__ void __launch_bounds__(192, 2)
crf_kernel(const float* __restrict__ emis,
           const int*   __restrict__ tagsw,   // int32 view; int64 auto-detected
           const int*   __restrict__ mask,
           const float* __restrict__ trans,
           const float* __restrict__ startT,
           const float* __restrict__ endT,
           float* __restrict__ out)
{
    __shared__ __align__(16) float2 bufs[6][2][32];  // [warp][double-buf][lane]
    __shared__ float shP[48], shR[48], shC[6];
    __shared__ float shRed[192];

    const int b   = blockIdx.x;
    const int tid = threadIdx.x;
    const int w   = tid >> 5;
    const int l   = tid & 31;
    const bool act = l < 24;
    const int j0 = act ? 2*l     : 0;
    const int j1 = act ? 2*l + 1 : 0;

    const size_t base = (size_t)b * S * T;
    const bool fw = (w < 3);

    // per-lane exp(transition) pair constants (96 regs), transposed packing:
    // fw: EA[k]=(E[2k][j0],E[2k+1][j0]), EB[k]=(E[2k][j1],E[2k+1][j1])
    // bw: EA[k]=(E[j0][2k],E[j0][2k+1]), EB[k]=(E[j1][2k],E[j1][2k+1])
    u64 EA[24], EB[24];
    if (fw) {
#pragma unroll
        for (int k = 0; k < 24; ++k) {
            float a0 = __expf(trans[(2*k)*T   + j0]);
            float a1 = __expf(trans[(2*k+1)*T + j0]);
            float b0 = __expf(trans[(2*k)*T   + j1]);
            float b1 = __expf(trans[(2*k+1)*T + j1]);
            EA[k] = act ? pack2(a0, a1) : 0ull;
            EB[k] = act ? pack2(b0, b1) : 0ull;
        }
    } else {
#pragma unroll
        for (int k = 0; k < 24; ++k) {
            float a0 = __expf(trans[j0*T + 2*k]);
            float a1 = __expf(trans[j0*T + 2*k+1]);
            float b0 = __expf(trans[j1*T + 2*k]);
            float b1 = __expf(trans[j1*T + 2*k+1]);
            EA[k] = act ? pack2(a0, a1) : 0ull;
            EB[k] = act ? pack2(b0, b1) : 0ull;
        }
    }

    const float* ep0 = emis + base + j0;

    // runtime per-warp chain parameters (ONE run_chain instance per BW)
    const bool exact = (w == 0) || (w == 3);
    const int  niter = exact ? 341 : (w == 4) ? 374 : 373;
    const int  reset = exact ? -1 : 31;
    const float* ep =
        (w == 0) ? ep0 :
        (w == 1) ? ep0 + (size_t)309 * T :
        (w == 2) ? ep0 + (size_t)650 * T :
        (w == 3) ? ep0 :
        (w == 4) ? ep0 - (size_t)309 * T :
                   ep0 - (size_t)651 * T;

    float p0x, p0y;
    if (w == 0) {
        float2 e0 = *(const float2*)(ep0);                    // t = 0
        p0x = act ? __expf(startT[j0] + e0.x) : 0.f;
        p0y = act ? __expf(startT[j1] + e0.y) : 0.f;
    } else if (w == 3) {
        p0x = act ? __expf(endT[j0]) : 0.f;
        p0y = act ? __expf(endT[j1]) : 0.f;
    } else {
        p0x = act ? 1.f : 0.f;                                // uniform burn-in
        p0y = act ? 1.f : 0.f;
    }

    float pfx, pfy, cfin;
    if (fw) run_chain<0>(ep, EA, EB, p0x, p0y, niter, reset, l, bufs[w], pfx, pfy, cfin);
    else    run_chain<1>(ep, EA, EB, p0x, p0y, niter, reset, l, bufs[w], pfx, pfy, cfin);

    if (act) {
        if (w == 2) { shP[2*l] = pfx; shP[2*l+1] = pfy; }     // dir(alpha_1023)
        if (w == 5) { shR[2*l] = pfx; shR[2*l+1] = pfy; }     // dir(beta_1024)
    }
    if (l == 0) shC[w] = cfin;
    __syncthreads();

    shRed[tid] = (tid < 48) ? shP[tid] * shR[tid] : 0.f;
    __syncthreads();

    float Z = 0.f;
    if (tid == 0) {
        float dot = 0.f;
#pragma unroll
        for (int k = 0; k < 48; ++k) dot += shRed[k];
        Z = __logf(dot) + shC[0] + shC[1] + shC[2] + shC[3] + shC[4] + shC[5];
    }

    // ---- tags dtype detection: int64 iff sampled odd 32-bit words all zero ----
    int oddw = tagsw[2*tid + 1];
    int any  = __syncthreads_or(oddw != 0);          // also a barrier for shRed reuse
    const bool is64 = (any == 0);

    // ---- numerator: gold-path score ----
    const size_t tbase = (size_t)b * S;
    float num = 0.f;
#pragma unroll 4
    for (int s = tid; s < S; s += 192) {
        int cur = is64 ? tagsw[(tbase + s) * 2] : tagsw[tbase + s];
        if (s == 0) {
            num += startT[cur] + emis[base + cur];
        } else {
            int prev = is64 ? tagsw[(tbase + s - 1) * 2] : tagsw[tbase + s - 1];
            float m = (float)mask[tbase + s];
            num += (trans[prev*T + cur] + emis[base + (size_t)s*T + cur]) * m;
        }
        if (s == S - 1) num += endT[cur];
    }
    shRed[tid] = num;
    __syncthreads();
    if (tid == 0) {
        float tot = 0.f;
#pragma unroll
        for (int k = 0; k < 192; ++k) tot += shRed[k];
        out[b] = Z - tot;                            // NLL
    }
}

extern "C" void kernel_launch(void* const* d_in, const int* in_sizes, int n_in,
                              void* d_out, int out_size) {
    (void)in_sizes; (void)n_in; (void)out_size;
    crf_kernel<<<B, 192>>>(
        (const float*)d_in[0],   // emissions
        (const int*)  d_in[1],   // tags (i32 or i64, detected on device)
        (const int*)  d_in[2],   // mask
        (const float*)d_in[3],   // transitions
        (const float*)d_in[4],   // start_transitions
        (const float*)d_in[5],   // end_transitions
        (float*)d_out);
}